// round 12
// baseline (speedup 1.0000x reference)
#include <cuda_runtime.h>
#include <math_constants.h>

#define NNK     16
#define GSZ     32
#define NMAX    8192
#define NGMAX   (NMAX / GSZ)           // 256
#define NSLICE  8
#define GPS     (NGMAX / NSLICE)       // 32 groups per slice == warp size
#define NBUCK   32768
#define EPS     1e-4f

// ---------------- global scratch (static device memory) ---------------------
__device__ double g_sum_minrow, g_sum_mincol, g_sum_dens;   // finalize re-zeros
__device__ int    g_hist[4][NBUCK];                         // prefix_scatter re-zeros
__device__ int    g_off [4][NBUCK];                         // rewritten each call

// sorted clouds as float4(x,y,z,|p|^2): [cloud 0=pred,1=true][batch][i]
__device__ float4 g_pts  [2][2][NMAX];
__device__ float4 g_gbmin[2][2][NGMAX];
__device__ float4 g_gbmax[2][2][NGMAX];
// partial sorted top-16 d^2 lists: [task0/1][batch][slice 0..NSLICE-1, NSLICE=seed][k][i]
__device__ float  g_list [2][2][NSLICE + 1][NNK][NMAX];
// task2 partial minima: [batch][slice 0..NSLICE-1, NSLICE=seed][i]
__device__ float  g_mind [2][NSLICE + 1][NMAX];
// seed thresholds: [task][batch][i]
__device__ float  g_kappa[3][2][NMAX];

// ---------------- Morton helpers -------------------------------------------
__device__ __forceinline__ unsigned quant5(float v) {
    int q = (int)((v + 8.0f) * 2.0f);
    q = q < 0 ? 0 : (q > 31 ? 31 : q);
    return (unsigned)q;
}
__device__ __forceinline__ unsigned spread3(unsigned v) {
    unsigned r = 0;
#pragma unroll
    for (int b = 0; b < 5; b++) r |= ((v >> b) & 1u) << (3 * b);
    return r;
}
__device__ __forceinline__ unsigned morton15(float x, float y, float z) {
    return (spread3(quant5(x)) << 2) | (spread3(quant5(y)) << 1) | spread3(quant5(z));
}

// ---------------- 1: histogram ---------------------------------------------
__global__ void __launch_bounds__(256)
hist_kernel(const float* __restrict__ y_pred, const float* __restrict__ y_true, int N) {
    int cb    = blockIdx.y;
    int cloud = cb >> 1, batch = cb & 1;
    const float* src = (cloud ? y_true : y_pred) + (size_t)batch * N * 3;
    int i = blockIdx.x * 256 + threadIdx.x;
    if (i < N) {
        unsigned code = morton15(src[3*i], src[3*i+1], src[3*i+2]);
        atomicAdd(&g_hist[cb][code], 1);
    }
}

// ---------------- 2: prefix + scatter fused (one CTA per cloud,batch) -------
__global__ void __launch_bounds__(1024)
prefix_scatter_kernel(const float* __restrict__ y_pred,
                      const float* __restrict__ y_true, int N) {
    __shared__ int ts[1024];
    int cb    = blockIdx.x;
    int cloud = cb >> 1, batch = cb & 1;
    const float* src = (cloud ? y_true : y_pred) + (size_t)batch * N * 3;
    int t = threadIdx.x;

    const int CH = NBUCK / 1024;
    int base = t * CH;
    int s = 0;
#pragma unroll
    for (int j = 0; j < CH; j++) s += g_hist[cb][base + j];
    ts[t] = s;
    __syncthreads();
    for (int off = 1; off < 1024; off <<= 1) {
        int add = (t >= off) ? ts[t - off] : 0;
        __syncthreads();
        ts[t] += add;
        __syncthreads();
    }
    int running = (t == 0) ? 0 : ts[t - 1];
#pragma unroll
    for (int j = 0; j < CH; j++) {
        g_off[cb][base + j] = running;
        running += g_hist[cb][base + j];
    }
    __syncthreads();

    for (int i = t; i < N; i += 1024) {
        float x = src[3*i], y = src[3*i+1], z = src[3*i+2];
        unsigned code = morton15(x, y, z);
        int pos = atomicAdd(&g_off[cb][code], 1);
        g_pts[cloud][batch][pos] = make_float4(x, y, z, x*x + y*y + z*z);
    }
    for (int b = t; b < NBUCK; b += 1024) g_hist[cb][b] = 0;
}

// ---------------- top-k helpers ---------------------------------------------
__device__ __forceinline__ void topk_insert(float (&knn)[NNK], float d2) {
    float x = d2;
#pragma unroll
    for (int k = 0; k < NNK; k++) {
        float lo = fminf(knn[k], x);
        x        = fmaxf(knn[k], x);
        knn[k]   = lo;
    }
}

// ---------------- 3: seed kernel (+ warp-parallel bbox build) ----------------
__global__ void __launch_bounds__(128)
seed_kernel(int N) {
    __shared__ float4 sp[6 * GSZ];

    int task  = blockIdx.z;
    int batch = blockIdx.y;
    int i     = blockIdx.x * 128 + threadIdx.x;
    int NG    = N / GSZ;
    int lane  = threadIdx.x & 31;
    int wid   = threadIdx.x >> 5;
    int qc    = (task == 2) ? 0 : 1;
    int cc    = (task == 0) ? 0 : 1;
    const float4* pts = g_pts[cc][batch];

    // side duty (task 0 CTAs): build group bboxes, warp-parallel
    if (task == 0) {
        int widx = ((int)blockIdx.y * gridDim.x + (int)blockIdx.x) * 4 + wid;
        int totw = 2 * gridDim.x * 4;
        for (int j = widx; j < 4 * NG; j += totw) {
            int jcb = j / NG, g = j % NG;
            int jc = jcb >> 1, jb = jcb & 1;
            float4 p = g_pts[jc][jb][g * GSZ + lane];
            float mnx = p.x, mxx = p.x, mny = p.y, mxy = p.y, mnz = p.z, mxz = p.z;
#pragma unroll
            for (int o = 16; o > 0; o >>= 1) {
                mnx = fminf(mnx, __shfl_xor_sync(0xffffffffu, mnx, o));
                mxx = fmaxf(mxx, __shfl_xor_sync(0xffffffffu, mxx, o));
                mny = fminf(mny, __shfl_xor_sync(0xffffffffu, mny, o));
                mxy = fmaxf(mxy, __shfl_xor_sync(0xffffffffu, mxy, o));
                mnz = fminf(mnz, __shfl_xor_sync(0xffffffffu, mnz, o));
                mxz = fmaxf(mxz, __shfl_xor_sync(0xffffffffu, mxz, o));
            }
            if (lane == 0) {
                g_gbmin[jc][jb][g] = make_float4(mnx, mny, mnz, 0.f);
                g_gbmax[jc][jb][g] = make_float4(mxx, mxy, mxz, 0.f);
            }
        }
    }

    int gfirst = max(0, (int)blockIdx.x * 4 - 1);
    int glast  = min(NG - 1, (int)blockIdx.x * 4 + 4);
    int npts   = (glast - gfirst + 1) * GSZ;
    for (int t = threadIdx.x; t < npts; t += 128)
        sp[t] = pts[gfirst * GSZ + t];
    __syncthreads();

    float4 q = g_pts[qc][batch][i];
    float px = q.x, py = q.y, pz = q.z, x2 = q.w;
    float qx = -2.f * px, qy = -2.f * py, qz = -2.f * pz;

    int gseed = i / GSZ;
    int gs0 = max(0, gseed - 1), gs1 = min(NG - 1, gseed + 1);
    int lo = (gs0 - gfirst) * GSZ;
    int hi = (gs1 - gfirst + 1) * GSZ;

    if (task == 2) {
        float m = CUDART_INF_F;
#pragma unroll 8
        for (int t = lo; t < hi; t++) {
            float4 s  = sp[t];
            float  d2 = fmaf(qx, s.x, fmaf(qy, s.y, fmaf(qz, s.z, x2 + s.w)));
            m = fminf(m, d2);
        }
        g_mind[batch][NSLICE][i] = m;
        g_kappa[2][batch][i]     = m;
    } else {
        float knn[NNK];
#pragma unroll
        for (int k = 0; k < NNK; k++) knn[k] = CUDART_INF_F;
        float kmax = CUDART_INF_F;
#pragma unroll 8
        for (int t = lo; t < hi; t++) {
            float4 s  = sp[t];
            float  d2 = fmaf(qx, s.x, fmaf(qy, s.y, fmaf(qz, s.z, x2 + s.w)));
            if (d2 < kmax) { topk_insert(knn, d2); kmax = knn[NNK - 1]; }
        }
#pragma unroll
        for (int k = 0; k < NNK; k++)
            g_list[task][batch][NSLICE][k][i] = knn[k];
        g_kappa[task][batch][i] = knn[NNK - 1];
    }
}

// ---------------- 4: sliced scan, fused tasks, group-bbox-as-warp-bbox -------
// blockIdx.z in [0, 2*NSLICE): kind = z & 1 (0 = fused topk tasks 0+1,
// query=true; 1 = task2 mincol, query=pred), slice = z >> 1.
__global__ void __launch_bounds__(128)
scan_kernel(int N) {
    __shared__ float4   sbn[2][GPS], sbx[2][GPS];
    __shared__ unsigned s_wmask[4];
    __shared__ int      s_gids[GPS], s_slot[GPS];
    __shared__ float4   spk[GPS * GSZ];        // 16 KB, reused per cloud

    int z     = blockIdx.z;
    int kind  = z & 1;
    int slice = z >> 1;
    int batch = blockIdx.y;
    int i     = blockIdx.x * 128 + threadIdx.x;
    int NG    = N / GSZ;
    int g0    = slice * GPS;
    int lane  = threadIdx.x & 31;
    int wid   = threadIdx.x >> 5;

    int qc = kind ? 0 : 1;

    // stage candidate-slice bboxes (both clouds for fused kind)
    if (kind == 0) {
        for (int t = threadIdx.x; t < 2 * GPS; t += 128) {
            int c = t >> 5, g = t & 31;
            sbn[c][g] = g_gbmin[c][batch][g0 + g];
            sbx[c][g] = g_gbmax[c][batch][g0 + g];
        }
    } else {
        if (threadIdx.x < GPS) {
            sbn[1][threadIdx.x] = g_gbmin[1][batch][g0 + threadIdx.x];
            sbx[1][threadIdx.x] = g_gbmax[1][batch][g0 + threadIdx.x];
        }
    }

    float4 q = g_pts[qc][batch][i];
    float px = q.x, py = q.y, pz = q.z, x2 = q.w;
    float qx = -2.f * px, qy = -2.f * py, qz = -2.f * pz;

    int gseed = i / GSZ;                       // warp-uniform
    int gs0 = max(0, gseed - 1), gs1 = min(NG - 1, gseed + 1);

    // warp query bbox == query-cloud group bbox (no shuffles!)
    float4 wbn = g_gbmin[qc][batch][gseed];
    float4 wbx = g_gbmax[qc][batch][gseed];
    __syncthreads();

    int ncl = (kind == 0) ? 2 : 1;
    for (int ci = 0; ci < ncl; ci++) {
        int cc   = (kind == 0) ? ci : 1;       // candidate cloud
        int task = (kind == 0) ? ci : 2;
        const float4* pts = g_pts[cc][batch];

        float thr = g_kappa[task][batch][i] + EPS;
        float thrm = thr;
#pragma unroll
        for (int o = 16; o > 0; o >>= 1)
            thrm = fmaxf(thrm, __shfl_xor_sync(0xffffffffu, thrm, o));

        // coarse: lane-per-group, one ballot
        bool surv;
        {
            float4 bn = sbn[cc][lane], bx = sbx[cc][lane];
            float dx = fmaxf(0.f, fmaxf(bn.x - wbx.x, wbn.x - bx.x));
            float dy = fmaxf(0.f, fmaxf(bn.y - wbx.y, wbn.y - bx.y));
            float dz = fmaxf(0.f, fmaxf(bn.z - wbx.z, wbn.z - bx.z));
            surv = fmaf(dx, dx, fmaf(dy, dy, dz * dz)) <= thrm;
        }
        unsigned gmask = __ballot_sync(0xffffffffu, surv);

        // clear seed groups (warp-uniform)
        for (int g = gs0; g <= gs1; g++)
            if (g >= g0 && g < g0 + GPS) gmask &= ~(1u << (g - g0));

        // refine: per-lane exact point-vs-bbox with own threshold
        unsigned rmask = 0;
        unsigned mm = gmask;
        while (mm) {
            int g = __ffs(mm) - 1; mm &= mm - 1u;
            float4 bn = sbn[cc][g], bx = sbx[cc][g];
            float dx = fmaxf(0.f, fmaxf(bn.x - px, px - bx.x));
            float dy = fmaxf(0.f, fmaxf(bn.y - py, py - bx.y));
            float dz = fmaxf(0.f, fmaxf(bn.z - pz, pz - bx.z));
            float dmin2 = fmaf(dx, dx, fmaf(dy, dy, dz * dz));
            if (__any_sync(0xffffffffu, dmin2 <= thr)) rmask |= 1u << g;
        }
        if (lane == 0) s_wmask[wid] = rmask;
        __syncthreads();
        unsigned cta = s_wmask[0] | s_wmask[1] | s_wmask[2] | s_wmask[3];

        // compaction + selective staging
        if (threadIdx.x < GPS) {
            int slot = __popc(cta & ((1u << threadIdx.x) - 1u));
            s_slot[threadIdx.x] = slot;
            if (cta & (1u << threadIdx.x)) s_gids[slot] = threadIdx.x;
        }
        __syncthreads();
        int cnt = __popc(cta);
        for (int t = threadIdx.x; t < cnt * GSZ; t += 128)
            spk[t] = pts[(g0 + s_gids[t >> 5]) * GSZ + (t & 31)];
        __syncthreads();

        // rebased payload: d2' = d2 - x2
        if (task == 2) {
            float m = CUDART_INF_F;
            unsigned r = rmask;
            while (r) {
                int g = __ffs(r) - 1; r &= r - 1u;
                int base = s_slot[g] * GSZ;
#pragma unroll 8
                for (int t = 0; t < GSZ; t++) {
                    float4 sp = spk[base + t];
                    float  d2p = fmaf(qx, sp.x, fmaf(qy, sp.y, fmaf(qz, sp.z, sp.w)));
                    m = fminf(m, d2p);
                }
            }
            g_mind[batch][slice][i] = m + x2;     // INF stays INF
        } else {
            float knn[NNK];
#pragma unroll
            for (int k = 0; k < NNK; k++) knn[k] = CUDART_INF_F;
            float thrp = thr - x2;
            float bnd  = thrp;
            unsigned r = rmask;
            while (r) {
                int g = __ffs(r) - 1; r &= r - 1u;
                int base = s_slot[g] * GSZ;
#pragma unroll 8
                for (int t = 0; t < GSZ; t++) {
                    float4 sp = spk[base + t];
                    float  d2p = fmaf(qx, sp.x, fmaf(qy, sp.y, fmaf(qz, sp.z, sp.w)));
                    if (d2p < bnd) {
                        topk_insert(knn, d2p);
                        bnd = fminf(thrp, knn[NNK - 1]);
                    }
                }
            }
#pragma unroll
            for (int k = 0; k < NNK; k++)
                g_list[task][batch][slice][k][i] = knn[k] + x2;   // INF stays INF
        }
        __syncthreads();   // protect smem reuse across clouds
    }
}

// ---------------- merge helper: keep lowest 16 of two sorted asc lists ------
__device__ __forceinline__ void merge16(float (&A)[NNK], const float (&B)[NNK]) {
    float C[NNK];
#pragma unroll
    for (int i = 0; i < NNK; i++) C[i] = fminf(A[i], B[NNK - 1 - i]);
#pragma unroll
    for (int k = 8; k >= 1; k >>= 1) {
#pragma unroll
        for (int i = 0; i < NNK; i++) {
            if (!(i & k)) {
                float lo = fminf(C[i], C[i + k]);
                float hi = fmaxf(C[i], C[i + k]);
                C[i] = lo; C[i + k] = hi;
            }
        }
    }
#pragma unroll
    for (int i = 0; i < NNK; i++) A[i] = C[i];
}

// ---------------- 5: combine ------------------------------------------------
__global__ void __launch_bounds__(256)
combine_kernel(int N) {
    __shared__ float redA[8], redB[8], redC[8];
    int batch = blockIdx.y;
    int i = blockIdx.x * 256 + threadIdx.x;

    float A[NNK], Bt[NNK];
#pragma unroll
    for (int k = 0; k < NNK; k++) A[k] = g_list[0][batch][NSLICE][k][i];
    for (int s = 0; s < NSLICE; s++) {
        float Bl[NNK];
#pragma unroll
        for (int k = 0; k < NNK; k++) Bl[k] = g_list[0][batch][s][k][i];
        merge16(A, Bl);
    }
#pragma unroll
    for (int k = 0; k < NNK; k++) Bt[k] = g_list[1][batch][NSLICE][k][i];
    for (int s = 0; s < NSLICE; s++) {
        float Bl[NNK];
#pragma unroll
        for (int k = 0; k < NNK; k++) Bl[k] = g_list[1][batch][s][k][i];
        merge16(Bt, Bl);
    }

    float minr = sqrtf(fmaxf(A[0], 0.f));
    float dens = 0.f;
#pragma unroll
    for (int k = 0; k < NNK; k++) {
        float dp = sqrtf(fmaxf(A[k], 0.f));
        float dt = sqrtf(fmaxf(Bt[k], 0.f));
        dens += fabsf(dp - dt);
    }

    float m = CUDART_INF_F;
#pragma unroll
    for (int s = 0; s <= NSLICE; s++) m = fminf(m, g_mind[batch][s][i]);
    float mc = sqrtf(fmaxf(m, 0.f));

#pragma unroll
    for (int o = 16; o > 0; o >>= 1) {
        minr += __shfl_down_sync(0xffffffffu, minr, o);
        dens += __shfl_down_sync(0xffffffffu, dens, o);
        mc   += __shfl_down_sync(0xffffffffu, mc,   o);
    }
    if ((threadIdx.x & 31) == 0) {
        redA[threadIdx.x >> 5] = minr;
        redB[threadIdx.x >> 5] = dens;
        redC[threadIdx.x >> 5] = mc;
    }
    __syncthreads();
    if (threadIdx.x == 0) {
        float a = 0.f, b = 0.f, c = 0.f;
#pragma unroll
        for (int w = 0; w < 8; w++) { a += redA[w]; b += redB[w]; c += redC[w]; }
        atomicAdd(&g_sum_minrow, (double)a);
        atomicAdd(&g_sum_dens,   (double)b);
        atomicAdd(&g_sum_mincol, (double)c);
    }
}

// ---------------- 6: finalize -----------------------------------------------
__global__ void finalize_kernel(float* __restrict__ out, int BN) {
    double inv   = 1.0 / (double)BN;
    double shape = 0.5 * (g_sum_minrow * inv + g_sum_mincol * inv);
    double dens  = g_sum_dens / ((double)BN * (double)NNK);
    out[0] = (float)(shape + dens);
    out[1] = (float)shape;
    out[2] = (float)dens;
    g_sum_minrow = 0.0;
    g_sum_mincol = 0.0;
    g_sum_dens   = 0.0;
}

extern "C" void kernel_launch(void* const* d_in, const int* in_sizes, int n_in,
                              void* d_out, int out_size) {
    const float* y_pred = (const float*)d_in[0];
    const float* y_true = (const float*)d_in[1];
    const int B = 2, C = 3;
    int N = in_sizes[0] / (B * C);

    dim3 hgrid((N + 255) / 256, 4);
    hist_kernel          <<<hgrid, 256>>>(y_pred, y_true, N);
    prefix_scatter_kernel<<<4, 1024>>>(y_pred, y_true, N);
    dim3 segrid(N / 128, B, 3);
    seed_kernel          <<<segrid, 128>>>(N);
    dim3 scgrid(N / 128, B, 2 * NSLICE);
    scan_kernel          <<<scgrid, 128>>>(N);
    dim3 cgrid(N / 256, B);
    combine_kernel       <<<cgrid, 256>>>(N);
    finalize_kernel      <<<1, 1>>>((float*)d_out, B * N);
}

// round 13
// speedup vs baseline: 1.2093x; 1.2093x over previous
#include <cuda_runtime.h>
#include <math_constants.h>

#define NNK     16
#define GSZ     32
#define NMAX    8192
#define NGMAX   (NMAX / GSZ)           // 256
#define NSLICE  8
#define GPS     (NGMAX / NSLICE)       // 32 groups per slice == warp size
#define NBUCK   32768
#define EPS     1e-4f

// ---------------- global scratch (static device memory) ---------------------
__device__ double g_sum_minrow, g_sum_mincol, g_sum_dens;   // finalize re-zeros
__device__ int    g_hist[4][NBUCK];                         // scatter re-zeros
__device__ int    g_off [4][NBUCK];                         // rewritten each call

// sorted clouds as float4(x,y,z,|p|^2): [cloud 0=pred,1=true][batch][i]
__device__ float4 g_pts  [2][2][NMAX];
__device__ float4 g_gbmin[2][2][NGMAX];
__device__ float4 g_gbmax[2][2][NGMAX];
// partial sorted top-16 d^2 lists: [task0/1][batch][slice 0..NSLICE-1, NSLICE=seed][k][i]
__device__ float  g_list [2][2][NSLICE + 1][NNK][NMAX];
// task2 partial minima: [batch][slice 0..NSLICE-1, NSLICE=seed][i]
__device__ float  g_mind [2][NSLICE + 1][NMAX];
// seed thresholds: [task][batch][i]
__device__ float  g_kappa[3][2][NMAX];

// ---------------- Morton helpers -------------------------------------------
__device__ __forceinline__ unsigned quant5(float v) {
    int q = (int)((v + 8.0f) * 2.0f);
    q = q < 0 ? 0 : (q > 31 ? 31 : q);
    return (unsigned)q;
}
__device__ __forceinline__ unsigned spread3(unsigned v) {
    unsigned r = 0;
#pragma unroll
    for (int b = 0; b < 5; b++) r |= ((v >> b) & 1u) << (3 * b);
    return r;
}
__device__ __forceinline__ unsigned morton15(float x, float y, float z) {
    return (spread3(quant5(x)) << 2) | (spread3(quant5(y)) << 1) | spread3(quant5(z));
}

// ---------------- 1: histogram ---------------------------------------------
__global__ void __launch_bounds__(256)
hist_kernel(const float* __restrict__ y_pred, const float* __restrict__ y_true, int N) {
    int cb    = blockIdx.y;
    int cloud = cb >> 1, batch = cb & 1;
    const float* src = (cloud ? y_true : y_pred) + (size_t)batch * N * 3;
    int i = blockIdx.x * 256 + threadIdx.x;
    if (i < N) {
        unsigned code = morton15(src[3*i], src[3*i+1], src[3*i+2]);
        atomicAdd(&g_hist[cb][code], 1);
    }
}

// ---------------- 2: exclusive prefix per (cloud,batch) ---------------------
__global__ void __launch_bounds__(1024)
prefix_kernel() {
    __shared__ int ts[1024];
    int cb = blockIdx.x;
    int t  = threadIdx.x;
    const int CH = NBUCK / 1024;
    int base = t * CH;
    int s = 0;
#pragma unroll
    for (int j = 0; j < CH; j++) s += g_hist[cb][base + j];
    ts[t] = s;
    __syncthreads();
    for (int off = 1; off < 1024; off <<= 1) {
        int add = (t >= off) ? ts[t - off] : 0;
        __syncthreads();
        ts[t] += add;
        __syncthreads();
    }
    int running = (t == 0) ? 0 : ts[t - 1];
#pragma unroll
    for (int j = 0; j < CH; j++) {
        g_off[cb][base + j] = running;
        running += g_hist[cb][base + j];
    }
}

// ---------------- 3: scatter (wide) + re-zero hist ---------------------------
__global__ void __launch_bounds__(256)
scatter_kernel(const float* __restrict__ y_pred, const float* __restrict__ y_true, int N) {
    int cb    = blockIdx.y;
    int cloud = cb >> 1, batch = cb & 1;
    const float* src = (cloud ? y_true : y_pred) + (size_t)batch * N * 3;
    int i = blockIdx.x * 256 + threadIdx.x;
    if (i < N) {
        float x = src[3*i], y = src[3*i+1], z = src[3*i+2];
        unsigned code = morton15(x, y, z);
        int pos = atomicAdd(&g_off[cb][code], 1);
        g_pts[cloud][batch][pos] = make_float4(x, y, z, x*x + y*y + z*z);
    }
    int tidg = blockIdx.x * 256 + threadIdx.x;
    int per  = (NBUCK + (gridDim.x * 256) - 1) / (gridDim.x * 256);
    for (int j = 0; j < per; j++) {
        int b = tidg * per + j;
        if (b < NBUCK) g_hist[cb][b] = 0;
    }
}

// ---------------- top-k helpers ---------------------------------------------
__device__ __forceinline__ void topk_insert(float (&knn)[NNK], float d2) {
    float x = d2;
#pragma unroll
    for (int k = 0; k < NNK; k++) {
        float lo = fminf(knn[k], x);
        x        = fmaxf(knn[k], x);
        knn[k]   = lo;
    }
}

// ---------------- 4: seed kernel (+ warp-parallel bbox build) ----------------
__global__ void __launch_bounds__(128)
seed_kernel(int N) {
    __shared__ float4 sp[6 * GSZ];

    int task  = blockIdx.z;
    int batch = blockIdx.y;
    int i     = blockIdx.x * 128 + threadIdx.x;
    int NG    = N / GSZ;
    int lane  = threadIdx.x & 31;
    int wid   = threadIdx.x >> 5;
    int qc    = (task == 2) ? 0 : 1;
    int cc    = (task == 0) ? 0 : 1;
    const float4* pts = g_pts[cc][batch];

    // side duty (task 0 CTAs): build group bboxes, warp-parallel
    if (task == 0) {
        int widx = ((int)blockIdx.y * gridDim.x + (int)blockIdx.x) * 4 + wid;
        int totw = 2 * gridDim.x * 4;
        for (int j = widx; j < 4 * NG; j += totw) {
            int jcb = j / NG, g = j % NG;
            int jc = jcb >> 1, jb = jcb & 1;
            float4 p = g_pts[jc][jb][g * GSZ + lane];
            float mnx = p.x, mxx = p.x, mny = p.y, mxy = p.y, mnz = p.z, mxz = p.z;
#pragma unroll
            for (int o = 16; o > 0; o >>= 1) {
                mnx = fminf(mnx, __shfl_xor_sync(0xffffffffu, mnx, o));
                mxx = fmaxf(mxx, __shfl_xor_sync(0xffffffffu, mxx, o));
                mny = fminf(mny, __shfl_xor_sync(0xffffffffu, mny, o));
                mxy = fmaxf(mxy, __shfl_xor_sync(0xffffffffu, mxy, o));
                mnz = fminf(mnz, __shfl_xor_sync(0xffffffffu, mnz, o));
                mxz = fmaxf(mxz, __shfl_xor_sync(0xffffffffu, mxz, o));
            }
            if (lane == 0) {
                g_gbmin[jc][jb][g] = make_float4(mnx, mny, mnz, 0.f);
                g_gbmax[jc][jb][g] = make_float4(mxx, mxy, mxz, 0.f);
            }
        }
    }

    int gfirst = max(0, (int)blockIdx.x * 4 - 1);
    int glast  = min(NG - 1, (int)blockIdx.x * 4 + 4);
    int npts   = (glast - gfirst + 1) * GSZ;
    for (int t = threadIdx.x; t < npts; t += 128)
        sp[t] = pts[gfirst * GSZ + t];
    __syncthreads();

    float4 q = g_pts[qc][batch][i];
    float px = q.x, py = q.y, pz = q.z, x2 = q.w;
    float qx = -2.f * px, qy = -2.f * py, qz = -2.f * pz;

    int gseed = i / GSZ;
    int gs0 = max(0, gseed - 1), gs1 = min(NG - 1, gseed + 1);
    int lo = (gs0 - gfirst) * GSZ;
    int hi = (gs1 - gfirst + 1) * GSZ;

    if (task == 2) {
        float m = CUDART_INF_F;
#pragma unroll 8
        for (int t = lo; t < hi; t++) {
            float4 s  = sp[t];
            float  d2 = fmaf(qx, s.x, fmaf(qy, s.y, fmaf(qz, s.z, x2 + s.w)));
            m = fminf(m, d2);
        }
        g_mind[batch][NSLICE][i] = m;
        g_kappa[2][batch][i]     = m;
    } else {
        float knn[NNK];
#pragma unroll
        for (int k = 0; k < NNK; k++) knn[k] = CUDART_INF_F;
        float kmax = CUDART_INF_F;
#pragma unroll 8
        for (int t = lo; t < hi; t++) {
            float4 s  = sp[t];
            float  d2 = fmaf(qx, s.x, fmaf(qy, s.y, fmaf(qz, s.z, x2 + s.w)));
            if (d2 < kmax) { topk_insert(knn, d2); kmax = knn[NNK - 1]; }
        }
#pragma unroll
        for (int k = 0; k < NNK; k++)
            g_list[task][batch][NSLICE][k][i] = knn[k];
        g_kappa[task][batch][i] = knn[NNK - 1];
    }
}

// ---------------- 5: sliced scan (R9 structure + cheap warp bbox) ------------
// blockIdx.z = task*NSLICE + slice
__global__ void __launch_bounds__(128)
scan_kernel(int N) {
    __shared__ float4   sbmin[GPS], sbmax[GPS];
    __shared__ unsigned s_wmask[4];
    __shared__ int      s_gids[GPS], s_slot[GPS];
    __shared__ float4   spk[GPS * GSZ];

    int task  = blockIdx.z / NSLICE;
    int slice = blockIdx.z % NSLICE;
    int batch = blockIdx.y;
    int i     = blockIdx.x * 128 + threadIdx.x;
    int NG    = N / GSZ;
    int g0    = slice * GPS;
    int lane  = threadIdx.x & 31;
    int wid   = threadIdx.x >> 5;

    int qc = (task == 2) ? 0 : 1;
    int cc = (task == 0) ? 0 : 1;
    const float4* pts = g_pts[cc][batch];

    if (threadIdx.x < GPS) {
        sbmin[threadIdx.x] = g_gbmin[cc][batch][g0 + threadIdx.x];
    } else if (threadIdx.x < 2 * GPS) {
        sbmax[threadIdx.x - GPS] = g_gbmax[cc][batch][g0 + threadIdx.x - GPS];
    }

    float4 q = g_pts[qc][batch][i];
    float px = q.x, py = q.y, pz = q.z, x2 = q.w;
    float thr = g_kappa[task][batch][i] + EPS;

    int gseed = i / GSZ;                        // warp-uniform
    int gs0 = max(0, gseed - 1), gs1 = min(NG - 1, gseed + 1);

    // warp query bbox == query-cloud group bbox (2 uniform loads, no shuffles)
    float4 wbn = g_gbmin[qc][batch][gseed];
    float4 wbx = g_gbmax[qc][batch][gseed];
    // warp-max threshold (5 shuffles)
    float thrm = thr;
#pragma unroll
    for (int o = 16; o > 0; o >>= 1)
        thrm = fmaxf(thrm, __shfl_xor_sync(0xffffffffu, thrm, o));
    __syncthreads();

    // coarse: lane-per-group, one ballot
    bool surv;
    {
        float4 bn = sbmin[lane], bx = sbmax[lane];
        float dx = fmaxf(0.f, fmaxf(bn.x - wbx.x, wbn.x - bx.x));
        float dy = fmaxf(0.f, fmaxf(bn.y - wbx.y, wbn.y - bx.y));
        float dz = fmaxf(0.f, fmaxf(bn.z - wbx.z, wbn.z - bx.z));
        surv = fmaf(dx, dx, fmaf(dy, dy, dz * dz)) <= thrm;
    }
    unsigned gmask = __ballot_sync(0xffffffffu, surv);

    // clear seed groups (warp-uniform)
    for (int g = gs0; g <= gs1; g++)
        if (g >= g0 && g < g0 + GPS) gmask &= ~(1u << (g - g0));

    // refine: per-lane exact point-vs-bbox test with own threshold
    unsigned rmask = 0;
    unsigned mm = gmask;
    while (mm) {
        int g = __ffs(mm) - 1; mm &= mm - 1u;
        float4 bn = sbmin[g], bx = sbmax[g];
        float dx = fmaxf(0.f, fmaxf(bn.x - px, px - bx.x));
        float dy = fmaxf(0.f, fmaxf(bn.y - py, py - bx.y));
        float dz = fmaxf(0.f, fmaxf(bn.z - pz, pz - bx.z));
        float dmin2 = fmaf(dx, dx, fmaf(dy, dy, dz * dz));
        if (__any_sync(0xffffffffu, dmin2 <= thr)) rmask |= 1u << g;
    }
    if (lane == 0) s_wmask[wid] = rmask;
    __syncthreads();
    unsigned cta = s_wmask[0] | s_wmask[1] | s_wmask[2] | s_wmask[3];

    // compaction + selective staging of refined survivors
    if (threadIdx.x < GPS) {
        int slot = __popc(cta & ((1u << threadIdx.x) - 1u));
        s_slot[threadIdx.x] = slot;
        if (cta & (1u << threadIdx.x)) s_gids[slot] = threadIdx.x;
    }
    __syncthreads();
    int cnt = __popc(cta);
    for (int t = threadIdx.x; t < cnt * GSZ; t += 128)
        spk[t] = pts[(g0 + s_gids[t >> 5]) * GSZ + (t & 31)];
    __syncthreads();

    // rebased scan: d2' = d2 - x2
    float qx = -2.f * px, qy = -2.f * py, qz = -2.f * pz;

    if (task == 2) {
        float m = CUDART_INF_F;
        unsigned r = rmask;
        while (r) {
            int g = __ffs(r) - 1; r &= r - 1u;
            int base = s_slot[g] * GSZ;
#pragma unroll 8
            for (int t = 0; t < GSZ; t++) {
                float4 sp = spk[base + t];
                float  d2p = fmaf(qx, sp.x, fmaf(qy, sp.y, fmaf(qz, sp.z, sp.w)));
                m = fminf(m, d2p);
            }
        }
        g_mind[batch][slice][i] = m + x2;     // INF stays INF
    } else {
        float knn[NNK];
#pragma unroll
        for (int k = 0; k < NNK; k++) knn[k] = CUDART_INF_F;
        float thrp = thr - x2;
        float bnd  = thrp;
        unsigned r = rmask;
        while (r) {
            int g = __ffs(r) - 1; r &= r - 1u;
            int base = s_slot[g] * GSZ;
#pragma unroll 8
            for (int t = 0; t < GSZ; t++) {
                float4 sp = spk[base + t];
                float  d2p = fmaf(qx, sp.x, fmaf(qy, sp.y, fmaf(qz, sp.z, sp.w)));
                if (d2p < bnd) {
                    topk_insert(knn, d2p);
                    bnd = fminf(thrp, knn[NNK - 1]);
                }
            }
        }
#pragma unroll
        for (int k = 0; k < NNK; k++)
            g_list[task][batch][slice][k][i] = knn[k] + x2;   // INF stays INF
    }
}

// ---------------- merge helper: keep lowest 16 of two sorted asc lists ------
__device__ __forceinline__ void merge16(float (&A)[NNK], const float (&B)[NNK]) {
    float C[NNK];
#pragma unroll
    for (int i = 0; i < NNK; i++) C[i] = fminf(A[i], B[NNK - 1 - i]);
#pragma unroll
    for (int k = 8; k >= 1; k >>= 1) {
#pragma unroll
        for (int i = 0; i < NNK; i++) {
            if (!(i & k)) {
                float lo = fminf(C[i], C[i + k]);
                float hi = fmaxf(C[i], C[i + k]);
                C[i] = lo; C[i + k] = hi;
            }
        }
    }
#pragma unroll
    for (int i = 0; i < NNK; i++) A[i] = C[i];
}

// ---------------- 6: combine (128 thr, 2x CTAs) ------------------------------
__global__ void __launch_bounds__(128)
combine_kernel(int N) {
    __shared__ float redA[4], redB[4], redC[4];
    int batch = blockIdx.y;
    int i = blockIdx.x * 128 + threadIdx.x;

    float A[NNK], Bt[NNK];
#pragma unroll
    for (int k = 0; k < NNK; k++) A[k] = g_list[0][batch][NSLICE][k][i];
    for (int s = 0; s < NSLICE; s++) {
        float Bl[NNK];
#pragma unroll
        for (int k = 0; k < NNK; k++) Bl[k] = g_list[0][batch][s][k][i];
        merge16(A, Bl);
    }
#pragma unroll
    for (int k = 0; k < NNK; k++) Bt[k] = g_list[1][batch][NSLICE][k][i];
    for (int s = 0; s < NSLICE; s++) {
        float Bl[NNK];
#pragma unroll
        for (int k = 0; k < NNK; k++) Bl[k] = g_list[1][batch][s][k][i];
        merge16(Bt, Bl);
    }

    float minr = sqrtf(fmaxf(A[0], 0.f));
    float dens = 0.f;
#pragma unroll
    for (int k = 0; k < NNK; k++) {
        float dp = sqrtf(fmaxf(A[k], 0.f));
        float dt = sqrtf(fmaxf(Bt[k], 0.f));
        dens += fabsf(dp - dt);
    }

    float m = CUDART_INF_F;
#pragma unroll
    for (int s = 0; s <= NSLICE; s++) m = fminf(m, g_mind[batch][s][i]);
    float mc = sqrtf(fmaxf(m, 0.f));

#pragma unroll
    for (int o = 16; o > 0; o >>= 1) {
        minr += __shfl_down_sync(0xffffffffu, minr, o);
        dens += __shfl_down_sync(0xffffffffu, dens, o);
        mc   += __shfl_down_sync(0xffffffffu, mc,   o);
    }
    if ((threadIdx.x & 31) == 0) {
        redA[threadIdx.x >> 5] = minr;
        redB[threadIdx.x >> 5] = dens;
        redC[threadIdx.x >> 5] = mc;
    }
    __syncthreads();
    if (threadIdx.x == 0) {
        float a = 0.f, b = 0.f, c = 0.f;
#pragma unroll
        for (int w = 0; w < 4; w++) { a += redA[w]; b += redB[w]; c += redC[w]; }
        atomicAdd(&g_sum_minrow, (double)a);
        atomicAdd(&g_sum_dens,   (double)b);
        atomicAdd(&g_sum_mincol, (double)c);
    }
}

// ---------------- 7: finalize -----------------------------------------------
__global__ void finalize_kernel(float* __restrict__ out, int BN) {
    double inv   = 1.0 / (double)BN;
    double shape = 0.5 * (g_sum_minrow * inv + g_sum_mincol * inv);
    double dens  = g_sum_dens / ((double)BN * (double)NNK);
    out[0] = (float)(shape + dens);
    out[1] = (float)shape;
    out[2] = (float)dens;
    g_sum_minrow = 0.0;
    g_sum_mincol = 0.0;
    g_sum_dens   = 0.0;
}

extern "C" void kernel_launch(void* const* d_in, const int* in_sizes, int n_in,
                              void* d_out, int out_size) {
    const float* y_pred = (const float*)d_in[0];
    const float* y_true = (const float*)d_in[1];
    const int B = 2, C = 3;
    int N = in_sizes[0] / (B * C);

    dim3 wgrid((N + 255) / 256, 4);
    hist_kernel    <<<wgrid, 256>>>(y_pred, y_true, N);
    prefix_kernel  <<<4, 1024>>>();
    scatter_kernel <<<wgrid, 256>>>(y_pred, y_true, N);
    dim3 segrid(N / 128, B, 3);
    seed_kernel    <<<segrid, 128>>>(N);
    dim3 scgrid(N / 128, B, 3 * NSLICE);
    scan_kernel    <<<scgrid, 128>>>(N);
    dim3 cgrid(N / 128, B);
    combine_kernel <<<cgrid, 128>>>(N);
    finalize_kernel<<<1, 1>>>((float*)d_out, B * N);
}